// round 11
// baseline (speedup 1.0000x reference)
#include <cuda_runtime.h>
#include <math.h>

// Problem constants
#define Bb   16
#define Tt   32
#define Ss   128
#define Ff   3
#define Hh   256
#define NHh  8
#define DKk  32
#define TPp  4
#define BSr  2048            // B*S rows
#define KENC 528             // padded 3+256+256=515 -> 528
#define KDEC 768             // 256+256+256
#define NG   1024            // 4*H

// ---------------- device state / scratch (no allocations allowed) ----------------
__device__ float g_eh[BSr * Hh];
__device__ float g_ec[BSr * Hh];
__device__ float g_dh[BSr * Hh];
__device__ float g_q[BSr * Hh];
__device__ float g_k[BSr * Hh];
__device__ float g_v[BSr * Hh];
__device__ float g_code[BSr * Hh];
__device__ float g_zin[BSr * KDEC];      // concat input (enc ld=528, dec ld=768)
__device__ float g_wgpad[KENC * NG];     // zero-padded + column-permuted enc gate W
__device__ float g_wgdec[KDEC * NG];     // column-permuted dec gate W
__device__ float g_bgenc[NG];            // permuted enc gate bias
__device__ float g_bgdec[NG];            // permuted dec gate bias

__device__ __forceinline__ float sigf(float x) { return 1.f / (1.f + expf(-x)); }

// ---------------- prep: reset state, build permuted weights ----------------
// Permutation: new col p = 4*j + gate  <-> orig col = gate*256 + j.
// A 4-col quad [4j..4j+3] then holds (i,f,g,o) for h-index j.
__global__ void prep_kernel(const float* __restrict__ encWg, const float* __restrict__ decWg,
                            const float* __restrict__ encbg, const float* __restrict__ decbg)
{
    int idx = blockIdx.x * blockDim.x + threadIdx.x;
    int stride = gridDim.x * blockDim.x;
    for (int i = idx; i < BSr * Hh; i += stride) {
        g_eh[i] = 0.f; g_ec[i] = 0.f; g_dh[i] = 0.f;
    }
    for (int i = idx; i < KENC * NG; i += stride) {
        int r = i >> 10, p = i & 1023;
        int oc = ((p & 3) << 8) | (p >> 2);
        g_wgpad[i] = (r < 515) ? encWg[r * 1024 + oc] : 0.f;
    }
    for (int i = idx; i < KDEC * NG; i += stride) {
        int r = i >> 10, p = i & 1023;
        int oc = ((p & 3) << 8) | (p >> 2);
        g_wgdec[i] = decWg[r * 1024 + oc];
    }
    for (int i = idx; i < NG; i += stride) {
        int oc = ((i & 3) << 8) | (i >> 2);
        g_bgenc[i] = encbg[oc];
        g_bgdec[i] = decbg[oc];
    }
}

// ---- double-buffered fp32 GEMM: BM=128, BN=128, BK=16, 256 thr, 8x8 microtile ----
// mode 0: plain -> C          mode 2: sigmoid(x+bias) -> C
// mode 3: LSTM update, write Cst (c_new) and Hst (h_new)   [encoder]
// mode 4: LSTM update, write Hst only                       [decoder]
__device__ __forceinline__ void gemm_body(
    const float* __restrict__ A, const float* __restrict__ W,
    float* __restrict__ C, int K, int N,
    const float* __restrict__ bias, int mode,
    float* __restrict__ Cst, float* __restrict__ Hst)
{
    __shared__ float As[2][16 * 132];   // transposed A tile: [k][m], stride 132
    __shared__ float Bs[2][16 * 128];

    const int tid = threadIdx.x;
    const int m0  = blockIdx.y * 128;
    const int n0  = blockIdx.x * 128;

    // global-load mapping
    const int ar  = tid >> 2;             // 0..63 (+64)
    const int ac  = (tid & 3) << 2;       // 0,4,8,12
    const int br  = tid >> 4;             // 0..15
    const int bc  = (tid & 15) << 2;      // 0..60 (+64)
    // compute mapping: 16x16 thread grid, 8 rows x 8 cols each
    const int tx  = tid & 15;
    const int ty  = tid >> 4;

    const float* aptr0 = A + (long)(m0 + ar) * K + ac;
    const float* aptr1 = A + (long)(m0 + ar + 64) * K + ac;
    const float* bptr  = W + (long)br * N + n0 + bc;

    float acc[8][8];
    #pragma unroll
    for (int i = 0; i < 8; i++)
        #pragma unroll
        for (int j = 0; j < 8; j++) acc[i][j] = 0.f;

    const int nk = K >> 4;

    float4 pa0 = *(const float4*)(aptr0);
    float4 pa1 = *(const float4*)(aptr1);
    float4 pb0 = *(const float4*)(bptr);
    float4 pb1 = *(const float4*)(bptr + 64);
    {
        float* as = As[0];
        as[(ac + 0) * 132 + ar] = pa0.x;
        as[(ac + 1) * 132 + ar] = pa0.y;
        as[(ac + 2) * 132 + ar] = pa0.z;
        as[(ac + 3) * 132 + ar] = pa0.w;
        as[(ac + 0) * 132 + ar + 64] = pa1.x;
        as[(ac + 1) * 132 + ar + 64] = pa1.y;
        as[(ac + 2) * 132 + ar + 64] = pa1.z;
        as[(ac + 3) * 132 + ar + 64] = pa1.w;
        *(float4*)&Bs[0][br * 128 + bc] = pb0;
        *(float4*)&Bs[0][br * 128 + bc + 64] = pb1;
    }
    __syncthreads();

    for (int t = 0; t < nk; t++) {
        const int cur = t & 1;
        if (t + 1 < nk) {
            int k0 = (t + 1) << 4;
            pa0 = *(const float4*)(aptr0 + k0);
            pa1 = *(const float4*)(aptr1 + k0);
            pb0 = *(const float4*)(bptr + (long)k0 * N);
            pb1 = *(const float4*)(bptr + (long)k0 * N + 64);
        }
        const float4* asr = (const float4*)As[cur];
        const float4* bsr = (const float4*)Bs[cur];
        #pragma unroll
        for (int kk = 0; kk < 16; kk++) {
            float4 aA = asr[kk * 33 + ty * 2];
            float4 aB = asr[kk * 33 + ty * 2 + 1];
            float4 bA = bsr[kk * 32 + tx * 2];
            float4 bB = bsr[kk * 32 + tx * 2 + 1];
            float a[8] = {aA.x, aA.y, aA.z, aA.w, aB.x, aB.y, aB.z, aB.w};
            float b[8] = {bA.x, bA.y, bA.z, bA.w, bB.x, bB.y, bB.z, bB.w};
            #pragma unroll
            for (int i = 0; i < 8; i++)
                #pragma unroll
                for (int j = 0; j < 8; j++)
                    acc[i][j] = fmaf(a[i], b[j], acc[i][j]);
        }
        if (t + 1 < nk) {
            const int nxt = cur ^ 1;
            float* as = As[nxt];
            as[(ac + 0) * 132 + ar] = pa0.x;
            as[(ac + 1) * 132 + ar] = pa0.y;
            as[(ac + 2) * 132 + ar] = pa0.z;
            as[(ac + 3) * 132 + ar] = pa0.w;
            as[(ac + 0) * 132 + ar + 64] = pa1.x;
            as[(ac + 1) * 132 + ar + 64] = pa1.y;
            as[(ac + 2) * 132 + ar + 64] = pa1.z;
            as[(ac + 3) * 132 + ar + 64] = pa1.w;
            *(float4*)&Bs[nxt][br * 128 + bc] = pb0;
            *(float4*)&Bs[nxt][br * 128 + bc + 64] = pb1;
        }
        __syncthreads();
    }

    if (mode <= 2) {
        float4 bv0 = make_float4(0.f, 0.f, 0.f, 0.f), bv1 = bv0;
        if (mode >= 1) {
            bv0 = *(const float4*)(bias + n0 + tx * 8);
            bv1 = *(const float4*)(bias + n0 + tx * 8 + 4);
        }
        #pragma unroll
        for (int i = 0; i < 8; i++) {
            int m = m0 + ty * 8 + i;
            float4 v0 = make_float4(acc[i][0], acc[i][1], acc[i][2], acc[i][3]);
            float4 v1 = make_float4(acc[i][4], acc[i][5], acc[i][6], acc[i][7]);
            if (mode >= 1) {
                v0.x += bv0.x; v0.y += bv0.y; v0.z += bv0.z; v0.w += bv0.w;
                v1.x += bv1.x; v1.y += bv1.y; v1.z += bv1.z; v1.w += bv1.w;
            }
            if (mode == 2) {
                v0.x = sigf(v0.x); v0.y = sigf(v0.y); v0.z = sigf(v0.z); v0.w = sigf(v0.w);
                v1.x = sigf(v1.x); v1.y = sigf(v1.y); v1.z = sigf(v1.z); v1.w = sigf(v1.w);
            }
            *(float4*)(C + (long)m * N + n0 + tx * 8) = v0;
            *(float4*)(C + (long)m * N + n0 + tx * 8 + 4) = v1;
        }
    } else {
        // fused LSTM epilogue: this thread's 8 cols = 2 (i,f,g,o) quads
        float b8[8];
        #pragma unroll
        for (int j = 0; j < 8; j++) b8[j] = bias[n0 + tx * 8 + j];
        const int hbase = (n0 >> 2) + (tx << 1);
        #pragma unroll
        for (int i = 0; i < 8; i++) {
            int m = m0 + ty * 8 + i;
            #pragma unroll
            for (int q = 0; q < 2; q++) {
                float zi = acc[i][q * 4 + 0] + b8[q * 4 + 0];
                float zf = acc[i][q * 4 + 1] + b8[q * 4 + 1];
                float zg = acc[i][q * 4 + 2] + b8[q * 4 + 2];
                float zo = acc[i][q * 4 + 3] + b8[q * 4 + 3];
                long idx = (long)m * Hh + hbase + q;
                float c  = Cst[idx];
                float cn = sigf(zf) * c + sigf(zi) * tanhf(zg);
                float hn = sigf(zo) * tanhf(cn);
                if (mode == 3) Cst[idx] = cn;
                Hst[idx] = hn;
            }
        }
    }
}

__global__ void __launch_bounds__(256) gemm_kernel(
    const float* __restrict__ A, const float* __restrict__ W, float* __restrict__ C,
    int K, int N, const float* __restrict__ bias, int mode,
    float* __restrict__ Cst, float* __restrict__ Hst)
{
    gemm_body(A, W, C, K, N, bias, mode, Cst, Hst);
}

// QKV (+ optional emb as z==3): z=0..2 qkv from Ah; z=3 emb from Ae w/ sigmoid+bias
__global__ void __launch_bounds__(256) gemmqkv_kernel(
    const float* __restrict__ Ah, const float* __restrict__ Ae,
    const float* __restrict__ Wq, const float* __restrict__ Wk, const float* __restrict__ Wv,
    const float* __restrict__ We, const float* __restrict__ embb,
    float* __restrict__ Cq, float* __restrict__ Ck, float* __restrict__ Cv,
    float* __restrict__ Ce)
{
    int z = blockIdx.z;
    if (z == 0)      gemm_body(Ah, Wq, Cq, Hh, Hh, 0, 0, 0, 0);
    else if (z == 1) gemm_body(Ah, Wk, Ck, Hh, Hh, 0, 0, 0, 0);
    else if (z == 2) gemm_body(Ah, Wv, Cv, Hh, Hh, 0, 0, 0, 0);
    else             gemm_body(Ae, We, Ce, Hh, Hh, embb, 2, 0, 0);
}

// ---------------- attention + concat assembly ----------------
__global__ void __launch_bounds__(256) attn_kernel(
    const float* __restrict__ Q, const float* __restrict__ Km, const float* __restrict__ Vm,
    const float* __restrict__ Hs, const float* __restrict__ Xs,
    int xmode, int t, float* __restrict__ Z, int ldz, int xlen)
{
    const int row0 = blockIdx.x << 3;
    const int tid = threadIdx.x;

    if (tid < 64) {
        const int row  = row0 + (tid >> 3);
        const int head = tid & 7;
        const int b = row >> 7;
        const int s = row & 127;
        const float* qp = Q + (long)row * Hh + head * DKk;
        float qv[DKk];
        #pragma unroll
        for (int d = 0; d < DKk; d++) qv[d] = qp[d];

        const int offs[4] = {2, 1, -1, -2};
        float sc[4];
        #pragma unroll
        for (int j = 0; j < 4; j++) {
            int sn = s + offs[j];
            float a = 0.f;
            if (sn >= 0 && sn < Ss) {
                const float* kp = Km + (long)(b * Ss + sn) * Hh + head * DKk;
                #pragma unroll
                for (int d = 0; d < DKk; d++) a = fmaf(qv[d], kp[d], a);
            }
            sc[j] = a * 0.17677669529663687f;   // 1/sqrt(32)
        }
        float mx = fmaxf(fmaxf(sc[0], sc[1]), fmaxf(sc[2], sc[3]));
        float e[4], ssum = 0.f;
        #pragma unroll
        for (int j = 0; j < 4; j++) { e[j] = expf(sc[j] - mx); ssum += e[j]; }
        float inv = 1.f / ssum;

        float ctx[DKk];
        #pragma unroll
        for (int d = 0; d < DKk; d++) ctx[d] = 0.f;
        #pragma unroll
        for (int j = 0; j < 4; j++) {
            int sn = s + offs[j];
            if (sn >= 0 && sn < Ss) {
                const float* vp = Vm + (long)(b * Ss + sn) * Hh + head * DKk;
                float w = e[j] * inv;
                #pragma unroll
                for (int d = 0; d < DKk; d++) ctx[d] = fmaf(w, vp[d], ctx[d]);
            }
        }
        float* zp = Z + (long)row * ldz + xlen + Hh + head * DKk;
        #pragma unroll
        for (int d = 0; d < DKk; d++) zp[d] = ctx[d];
    }

    // copy h into concat slot [xlen, xlen+H)
    for (int i = tid; i < 8 * Hh; i += 256) {
        int r = row0 + (i >> 8);
        int c = i & 255;
        Z[(long)r * ldz + xlen + c] = Hs[(long)r * Hh + c];
    }
    // copy x into concat slot [0, xlen)
    if (xmode == 0) {                      // encoder: x = input_data[b, t, s, :]
        for (int i = tid; i < 8 * Ff; i += 256) {
            int r = row0 + i / Ff;
            int f = i - (i / Ff) * Ff;
            int b = r >> 7, s = r & 127;
            Z[(long)r * ldz + f] = Xs[(((long)b * Tt + t) * Ss + s) * Ff + f];
        }
    } else {                               // decoder: x = code [row, H]
        for (int i = tid; i < 8 * Hh; i += 256) {
            int r = row0 + (i >> 8);
            int c = i & 255;
            Z[(long)r * ldz + c] = Xs[(long)r * Hh + c];
        }
    }
}

// ---------------- output head: out/In/num assembly ----------------
__global__ void __launch_bounds__(128) out_kernel(
    const float* __restrict__ Dh, const float* __restrict__ outW,
    const float* __restrict__ outB, const float* __restrict__ inp,
    int t, float* __restrict__ Out)
{
    int b = blockIdx.x;
    int s = threadIdx.x;     // 128
    __shared__ float osh[Ss];
    const float* hp = Dh + (long)(b * Ss + s) * Hh;
    float acc = 0.f;
    #pragma unroll 8
    for (int d = 0; d < Hh; d++) acc = fmaf(hp[d], outW[d], acc);
    float o = acc + outB[0];
    osh[s] = o;
    __syncthreads();
    float In  = (s == 0) ? inp[(((long)b * Tt + (t + 1)) * Ss + 0) * Ff + 1] : osh[s - 1];
    float num = inp[(((long)b * Tt + t) * Ss + s) * Ff + 2] + In - o;
    if (t >= TPp) {
        float* op = Out + (((long)b * (Tt - 1 - TPp) + (t - TPp)) * Ss + s) * 3;
        op[0] = o; op[1] = In; op[2] = num;
    }
}

// ---------------- host launch ----------------
static float* symaddr(const void* sym)
{
    void* p = 0;
    cudaGetSymbolAddress(&p, sym);
    return (float*)p;
}

extern "C" void kernel_launch(void* const* d_in, const int* in_sizes, int n_in,
                              void* d_out, int out_size)
{
    const float* input = (const float*)d_in[0];
    const float* encWq = (const float*)d_in[1];
    const float* encWk = (const float*)d_in[2];
    const float* encWv = (const float*)d_in[3];
    const float* encWg = (const float*)d_in[4];
    const float* encbg = (const float*)d_in[5];
    const float* decWq = (const float*)d_in[6];
    const float* decWk = (const float*)d_in[7];
    const float* decWv = (const float*)d_in[8];
    const float* decWg = (const float*)d_in[9];
    const float* decbg = (const float*)d_in[10];
    const float* embW  = (const float*)d_in[11];
    const float* embb  = (const float*)d_in[12];
    const float* outW  = (const float*)d_in[13];
    const float* outB  = (const float*)d_in[14];
    float* out = (float*)d_out;

    float* p_eh   = symaddr(g_eh);
    float* p_ec   = symaddr(g_ec);
    float* p_dh   = symaddr(g_dh);
    float* p_q    = symaddr(g_q);
    float* p_k    = symaddr(g_k);
    float* p_v    = symaddr(g_v);
    float* p_code = symaddr(g_code);
    float* p_zin  = symaddr(g_zin);
    float* p_wgp  = symaddr(g_wgpad);
    float* p_wgd  = symaddr(g_wgdec);
    float* p_bge  = symaddr(g_bgenc);
    float* p_bgd  = symaddr(g_bgdec);

    prep_kernel<<<256, 256>>>(encWg, decWg, encbg, decbg);

    dim3 gQKV3(Hh / 128, BSr / 128, 3);       // enc qkv
    dim3 gQKV4(Hh / 128, BSr / 128, 4);       // dec qkv + emb
    dim3 gWg(NG / 128, BSr / 128);            // gate GEMMs (fused LSTM epilogue)

    for (int t = 0; t < Tt - 1; t++) {
        // ---- encoder cell ----
        gemmqkv_kernel<<<gQKV3, 256>>>(p_eh, p_eh, encWq, encWk, encWv, embW, embb,
                                       p_q, p_k, p_v, p_code);
        attn_kernel<<<BSr / 8, 256>>>(p_q, p_k, p_v, p_eh, input, 0, t, p_zin, KENC, Ff);
        gemm_kernel<<<gWg, 256>>>(p_zin, p_wgp, 0, KENC, NG, p_bge, 3, p_ec, p_eh);
        // ---- dec qkv (from old dh) + emb code (from new eh), one launch ----
        gemmqkv_kernel<<<gQKV4, 256>>>(p_dh, p_eh, decWq, decWk, decWv, embW, embb,
                                       p_q, p_k, p_v, p_code);
        attn_kernel<<<BSr / 8, 256>>>(p_q, p_k, p_v, p_dh, p_code, 1, t, p_zin, KDEC, Hh);
        gemm_kernel<<<gWg, 256>>>(p_zin, p_wgd, 0, KDEC, NG, p_bgd, 4, p_dh, p_dh);
        // ---- output head ----
        out_kernel<<<Bb, Ss>>>(p_dh, outW, outB, input, t, out);
    }
}

// round 14
// speedup vs baseline: 1.1740x; 1.1740x over previous
#include <cuda_runtime.h>
#include <math.h>

// Problem constants
#define Bb   16
#define Tt   32
#define Ss   128
#define Ff   3
#define Hh   256
#define NHh  8
#define DKk  32
#define TPp  4
#define BSr  2048            // B*S rows
#define KENC 528             // padded 3+256+256=515 -> 528
#define KDEC 768             // 256+256+256
#define NG   1024            // 4*H

// ---------------- device state / scratch (no allocations allowed) ----------------
__device__ float g_eh[BSr * Hh];
__device__ float g_ec[BSr * Hh];
__device__ float g_dh[BSr * Hh];
__device__ float g_q[BSr * Hh];
__device__ float g_k[BSr * Hh];
__device__ float g_v[BSr * Hh];
__device__ float g_code[BSr * Hh];
__device__ float g_zin[BSr * KDEC];      // concat input (enc ld=528, dec ld=768)
__device__ float g_wgpad[KENC * NG];     // zero-padded + column-permuted enc gate W
__device__ float g_wgdec[KDEC * NG];     // column-permuted dec gate W
__device__ float g_bgenc[NG];            // permuted enc gate bias
__device__ float g_bgdec[NG];            // permuted dec gate bias

__device__ __forceinline__ float sigf(float x) { return 1.f / (1.f + expf(-x)); }

// ---------------- prep: reset state, build permuted weights ----------------
// Permutation: new col p = 4*j + gate  <-> orig col = gate*256 + j.
__global__ void prep_kernel(const float* __restrict__ encWg, const float* __restrict__ decWg,
                            const float* __restrict__ encbg, const float* __restrict__ decbg)
{
    int idx = blockIdx.x * blockDim.x + threadIdx.x;
    int stride = gridDim.x * blockDim.x;
    for (int i = idx; i < BSr * Hh; i += stride) {
        g_eh[i] = 0.f; g_ec[i] = 0.f; g_dh[i] = 0.f;
    }
    for (int i = idx; i < KENC * NG; i += stride) {
        int r = i >> 10, p = i & 1023;
        int oc = ((p & 3) << 8) | (p >> 2);
        g_wgpad[i] = (r < 515) ? encWg[r * 1024 + oc] : 0.f;
    }
    for (int i = idx; i < KDEC * NG; i += stride) {
        int r = i >> 10, p = i & 1023;
        int oc = ((p & 3) << 8) | (p >> 2);
        g_wgdec[i] = decWg[r * 1024 + oc];
    }
    for (int i = idx; i < NG; i += stride) {
        int oc = ((i & 3) << 8) | (i >> 2);
        g_bgenc[i] = encbg[oc];
        g_bgdec[i] = decbg[oc];
    }
}

// ---- double-buffered fp32 GEMM: BM=128, BN=64, BK=16, 256 thr, 8x4 microtile ----
// (R5-verified shape: ~103 regs, 25KB smem -> 2 CTAs/SM, enforced via launch_bounds)
// mode 0: plain -> C          mode 2: sigmoid(x+bias) -> C
// mode 3: LSTM update, write Cst (c_new) and Hst (h_new)   [encoder]
// mode 4: LSTM update, write Hst only                       [decoder]
__device__ __forceinline__ void gemm_body(
    const float* __restrict__ A, const float* __restrict__ W,
    float* __restrict__ C, int K, int N,
    const float* __restrict__ bias, int mode,
    float* __restrict__ Cst, float* __restrict__ Hst)
{
    // As stored transposed: As[stage][k][m], row stride 132 floats (=33 float4)
    __shared__ float As[2][16 * 132];
    __shared__ float Bs[2][16 * 64];

    const int tid = threadIdx.x;
    const int m0  = blockIdx.y * 128;
    const int n0  = blockIdx.x * 64;

    // global-load mapping
    const int ar  = tid >> 2;             // 0..63 (and +64)
    const int ac  = (tid & 3) << 2;       // 0,4,8,12
    const int br  = tid >> 4;             // 0..15
    const int bc  = (tid & 15) << 2;      // 0..60
    // compute mapping
    const int tx  = tid & 15;             // 0..15 -> 4 cols
    const int ty  = tid >> 4;             // 0..15 -> 8 rows

    const float* aptr0 = A + (long)(m0 + ar) * K + ac;
    const float* aptr1 = A + (long)(m0 + ar + 64) * K + ac;
    const float* bptr  = W + (long)br * N + n0 + bc;

    float acc[8][4];
    #pragma unroll
    for (int i = 0; i < 8; i++)
        #pragma unroll
        for (int j = 0; j < 4; j++) acc[i][j] = 0.f;

    const int nk = K >> 4;

    // preload tile 0
    float4 pa0 = *(const float4*)(aptr0);
    float4 pa1 = *(const float4*)(aptr1);
    float4 pb  = *(const float4*)(bptr);
    {
        float* as = As[0];
        as[(ac + 0) * 132 + ar] = pa0.x;
        as[(ac + 1) * 132 + ar] = pa0.y;
        as[(ac + 2) * 132 + ar] = pa0.z;
        as[(ac + 3) * 132 + ar] = pa0.w;
        as[(ac + 0) * 132 + ar + 64] = pa1.x;
        as[(ac + 1) * 132 + ar + 64] = pa1.y;
        as[(ac + 2) * 132 + ar + 64] = pa1.z;
        as[(ac + 3) * 132 + ar + 64] = pa1.w;
        *(float4*)&Bs[0][br * 64 + bc] = pb;
    }
    __syncthreads();

    for (int t = 0; t < nk; t++) {
        const int cur = t & 1;
        if (t + 1 < nk) {
            int k0 = (t + 1) << 4;
            pa0 = *(const float4*)(aptr0 + k0);
            pa1 = *(const float4*)(aptr1 + k0);
            pb  = *(const float4*)(bptr + (long)k0 * N);
        }
        const float4* asr = (const float4*)As[cur];
        const float4* bsr = (const float4*)Bs[cur];
        #pragma unroll
        for (int kk = 0; kk < 16; kk++) {
            float4 aA = asr[kk * 33 + ty * 2];
            float4 aB = asr[kk * 33 + ty * 2 + 1];
            float4 bb = bsr[kk * 16 + tx];
            float a[8] = {aA.x, aA.y, aA.z, aA.w, aB.x, aB.y, aB.z, aB.w};
            float b[4] = {bb.x, bb.y, bb.z, bb.w};
            #pragma unroll
            for (int i = 0; i < 8; i++)
                #pragma unroll
                for (int j = 0; j < 4; j++)
                    acc[i][j] = fmaf(a[i], b[j], acc[i][j]);
        }
        if (t + 1 < nk) {
            const int nxt = cur ^ 1;
            float* as = As[nxt];
            as[(ac + 0) * 132 + ar] = pa0.x;
            as[(ac + 1) * 132 + ar] = pa0.y;
            as[(ac + 2) * 132 + ar] = pa0.z;
            as[(ac + 3) * 132 + ar] = pa0.w;
            as[(ac + 0) * 132 + ar + 64] = pa1.x;
            as[(ac + 1) * 132 + ar + 64] = pa1.y;
            as[(ac + 2) * 132 + ar + 64] = pa1.z;
            as[(ac + 3) * 132 + ar + 64] = pa1.w;
            *(float4*)&Bs[nxt][br * 64 + bc] = pb;
        }
        __syncthreads();
    }

    if (mode <= 2) {
        float4 bv = make_float4(0.f, 0.f, 0.f, 0.f);
        if (mode >= 1) bv = *(const float4*)(bias + n0 + (tx << 2));
        #pragma unroll
        for (int i = 0; i < 8; i++) {
            int m = m0 + ty * 8 + i;
            float4 v = make_float4(acc[i][0], acc[i][1], acc[i][2], acc[i][3]);
            if (mode >= 1) { v.x += bv.x; v.y += bv.y; v.z += bv.z; v.w += bv.w; }
            if (mode == 2) { v.x = sigf(v.x); v.y = sigf(v.y); v.z = sigf(v.z); v.w = sigf(v.w); }
            *(float4*)(C + (long)m * N + n0 + (tx << 2)) = v;
        }
    } else {
        // fused LSTM epilogue: this thread's 4 cols = one (i,f,g,o) quad
        float b0 = bias[n0 + (tx << 2) + 0];
        float b1 = bias[n0 + (tx << 2) + 1];
        float b2 = bias[n0 + (tx << 2) + 2];
        float b3 = bias[n0 + (tx << 2) + 3];
        const int hbase = (n0 >> 2) + tx;   // h index in [0,255]
        #pragma unroll
        for (int i = 0; i < 8; i++) {
            int m = m0 + ty * 8 + i;
            float zi = acc[i][0] + b0;
            float zf = acc[i][1] + b1;
            float zg = acc[i][2] + b2;
            float zo = acc[i][3] + b3;
            long idx = (long)m * Hh + hbase;
            float c  = Cst[idx];
            float cn = sigf(zf) * c + sigf(zi) * tanhf(zg);
            float hn = sigf(zo) * tanhf(cn);
            if (mode == 3) Cst[idx] = cn;
            Hst[idx] = hn;
        }
    }
}

__global__ void __launch_bounds__(256, 2) gemm_kernel(
    const float* __restrict__ A, const float* __restrict__ W, float* __restrict__ C,
    int K, int N, const float* __restrict__ bias, int mode,
    float* __restrict__ Cst, float* __restrict__ Hst)
{
    gemm_body(A, W, C, K, N, bias, mode, Cst, Hst);
}

// QKV (+ optional emb as z==3): z=0..2 qkv from Ah; z=3 emb from Ae w/ sigmoid+bias
__global__ void __launch_bounds__(256, 2) gemmqkv_kernel(
    const float* __restrict__ Ah, const float* __restrict__ Ae,
    const float* __restrict__ Wq, const float* __restrict__ Wk, const float* __restrict__ Wv,
    const float* __restrict__ We, const float* __restrict__ embb,
    float* __restrict__ Cq, float* __restrict__ Ck, float* __restrict__ Cv,
    float* __restrict__ Ce)
{
    int z = blockIdx.z;
    if (z == 0)      gemm_body(Ah, Wq, Cq, Hh, Hh, 0, 0, 0, 0);
    else if (z == 1) gemm_body(Ah, Wk, Ck, Hh, Hh, 0, 0, 0, 0);
    else if (z == 2) gemm_body(Ah, Wv, Cv, Hh, Hh, 0, 0, 0, 0);
    else             gemm_body(Ae, We, Ce, Hh, Hh, embb, 2, 0, 0);
}

// ---------------- attention + concat assembly ----------------
__global__ void __launch_bounds__(256) attn_kernel(
    const float* __restrict__ Q, const float* __restrict__ Km, const float* __restrict__ Vm,
    const float* __restrict__ Hs, const float* __restrict__ Xs,
    int xmode, int t, float* __restrict__ Z, int ldz, int xlen)
{
    const int row0 = blockIdx.x << 3;
    const int tid = threadIdx.x;

    if (tid < 64) {
        const int row  = row0 + (tid >> 3);
        const int head = tid & 7;
        const int b = row >> 7;
        const int s = row & 127;
        const float* qp = Q + (long)row * Hh + head * DKk;
        float qv[DKk];
        #pragma unroll
        for (int d = 0; d < DKk; d++) qv[d] = qp[d];

        const int offs[4] = {2, 1, -1, -2};
        float sc[4];
        #pragma unroll
        for (int j = 0; j < 4; j++) {
            int sn = s + offs[j];
            float a = 0.f;
            if (sn >= 0 && sn < Ss) {
                const float* kp = Km + (long)(b * Ss + sn) * Hh + head * DKk;
                #pragma unroll
                for (int d = 0; d < DKk; d++) a = fmaf(qv[d], kp[d], a);
            }
            sc[j] = a * 0.17677669529663687f;   // 1/sqrt(32)
        }
        float mx = fmaxf(fmaxf(sc[0], sc[1]), fmaxf(sc[2], sc[3]));
        float e[4], ssum = 0.f;
        #pragma unroll
        for (int j = 0; j < 4; j++) { e[j] = expf(sc[j] - mx); ssum += e[j]; }
        float inv = 1.f / ssum;

        float ctx[DKk];
        #pragma unroll
        for (int d = 0; d < DKk; d++) ctx[d] = 0.f;
        #pragma unroll
        for (int j = 0; j < 4; j++) {
            int sn = s + offs[j];
            if (sn >= 0 && sn < Ss) {
                const float* vp = Vm + (long)(b * Ss + sn) * Hh + head * DKk;
                float w = e[j] * inv;
                #pragma unroll
                for (int d = 0; d < DKk; d++) ctx[d] = fmaf(w, vp[d], ctx[d]);
            }
        }
        float* zp = Z + (long)row * ldz + xlen + Hh + head * DKk;
        #pragma unroll
        for (int d = 0; d < DKk; d++) zp[d] = ctx[d];
    }

    // copy h into concat slot [xlen, xlen+H)
    for (int i = tid; i < 8 * Hh; i += 256) {
        int r = row0 + (i >> 8);
        int c = i & 255;
        Z[(long)r * ldz + xlen + c] = Hs[(long)r * Hh + c];
    }
    // copy x into concat slot [0, xlen)
    if (xmode == 0) {                      // encoder: x = input_data[b, t, s, :]
        for (int i = tid; i < 8 * Ff; i += 256) {
            int r = row0 + i / Ff;
            int f = i - (i / Ff) * Ff;
            int b = r >> 7, s = r & 127;
            Z[(long)r * ldz + f] = Xs[(((long)b * Tt + t) * Ss + s) * Ff + f];
        }
    } else {                               // decoder: x = code [row, H]
        for (int i = tid; i < 8 * Hh; i += 256) {
            int r = row0 + (i >> 8);
            int c = i & 255;
            Z[(long)r * ldz + c] = Xs[(long)r * Hh + c];
        }
    }
}

// ---------------- output head: out/In/num assembly ----------------
__global__ void __launch_bounds__(128) out_kernel(
    const float* __restrict__ Dh, const float* __restrict__ outW,
    const float* __restrict__ outB, const float* __restrict__ inp,
    int t, float* __restrict__ Out)
{
    int b = blockIdx.x;
    int s = threadIdx.x;     // 128
    __shared__ float osh[Ss];
    const float* hp = Dh + (long)(b * Ss + s) * Hh;
    float acc = 0.f;
    #pragma unroll 8
    for (int d = 0; d < Hh; d++) acc = fmaf(hp[d], outW[d], acc);
    float o = acc + outB[0];
    osh[s] = o;
    __syncthreads();
    float In  = (s == 0) ? inp[(((long)b * Tt + (t + 1)) * Ss + 0) * Ff + 1] : osh[s - 1];
    float num = inp[(((long)b * Tt + t) * Ss + s) * Ff + 2] + In - o;
    if (t >= TPp) {
        float* op = Out + (((long)b * (Tt - 1 - TPp) + (t - TPp)) * Ss + s) * 3;
        op[0] = o; op[1] = In; op[2] = num;
    }
}

// ---------------- host launch ----------------
static float* symaddr(const void* sym)
{
    void* p = 0;
    cudaGetSymbolAddress(&p, sym);
    return (float*)p;
}

extern "C" void kernel_launch(void* const* d_in, const int* in_sizes, int n_in,
                              void* d_out, int out_size)
{
    const float* input = (const float*)d_in[0];
    const float* encWq = (const float*)d_in[1];
    const float* encWk = (const float*)d_in[2];
    const float* encWv = (const float*)d_in[3];
    const float* encWg = (const float*)d_in[4];
    const float* encbg = (const float*)d_in[5];
    const float* decWq = (const float*)d_in[6];
    const float* decWk = (const float*)d_in[7];
    const float* decWv = (const float*)d_in[8];
    const float* decWg = (const float*)d_in[9];
    const float* decbg = (const float*)d_in[10];
    const float* embW  = (const float*)d_in[11];
    const float* embb  = (const float*)d_in[12];
    const float* outW  = (const float*)d_in[13];
    const float* outB  = (const float*)d_in[14];
    float* out = (float*)d_out;

    float* p_eh   = symaddr(g_eh);
    float* p_ec   = symaddr(g_ec);
    float* p_dh   = symaddr(g_dh);
    float* p_q    = symaddr(g_q);
    float* p_k    = symaddr(g_k);
    float* p_v    = symaddr(g_v);
    float* p_code = symaddr(g_code);
    float* p_zin  = symaddr(g_zin);
    float* p_wgp  = symaddr(g_wgpad);
    float* p_wgd  = symaddr(g_wgdec);
    float* p_bge  = symaddr(g_bgenc);
    float* p_bgd  = symaddr(g_bgdec);

    prep_kernel<<<256, 256>>>(encWg, decWg, encbg, decbg);

    dim3 gQKV3(Hh / 64, BSr / 128, 3);        // enc qkv
    dim3 gQKV4(Hh / 64, BSr / 128, 4);        // dec qkv + emb
    dim3 gWg(NG / 64, BSr / 128);             // gate GEMMs (fused LSTM epilogue)

    for (int t = 0; t < Tt - 1; t++) {
        // ---- encoder cell ----
        gemmqkv_kernel<<<gQKV3, 256>>>(p_eh, p_eh, encWq, encWk, encWv, embW, embb,
                                       p_q, p_k, p_v, p_code);
        attn_kernel<<<BSr / 8, 256>>>(p_q, p_k, p_v, p_eh, input, 0, t, p_zin, KENC, Ff);
        gemm_kernel<<<gWg, 256>>>(p_zin, p_wgp, 0, KENC, NG, p_bge, 3, p_ec, p_eh);
        // ---- dec qkv (from old dh) + emb code (from new eh), one launch ----
        gemmqkv_kernel<<<gQKV4, 256>>>(p_dh, p_eh, decWq, decWk, decWv, embW, embb,
                                       p_q, p_k, p_v, p_code);
        attn_kernel<<<BSr / 8, 256>>>(p_q, p_k, p_v, p_dh, p_code, 1, t, p_zin, KDEC, Hh);
        gemm_kernel<<<gWg, 256>>>(p_zin, p_wgd, 0, KDEC, NG, p_bgd, 4, p_dh, p_dh);
        // ---- output head ----
        out_kernel<<<Bb, Ss>>>(p_dh, outW, outB, input, t, out);
    }
}